// round 12
// baseline (speedup 1.0000x reference)
#include <cuda_runtime.h>
#include <cuda_fp16.h>
#include <stdint.h>
#include <math.h>

// ---------------- problem constants ----------------
#define HDIM   512
#define HEADS  16
#define HD     32
#define WS     8
#define L      64
#define NW     1024
#define NTOK   65536
#define IMG    256
#define NPIX   65536

typedef __half  fp16;
typedef __half2 fp162;

// ---------------- scratch ----------------
__device__ float g_win[(size_t)NTOK * HDIM];
__device__ float g_o1[(size_t)NTOK * HDIM];
__device__ __align__(16) fp16 g_xnb[(size_t)NTOK * HDIM];
__device__ __align__(16) fp16 g_qkvb[(size_t)NTOK * 3 * HDIM];
__device__ __align__(16) fp16 g_attb[(size_t)NTOK * HDIM];
__device__ __align__(16) fp16 g_hb[(size_t)NTOK * 4 * HDIM];
__device__ __align__(16) fp16 g_wq[(size_t)HDIM * 3 * HDIM];
__device__ __align__(16) fp16 g_wp[(size_t)HDIM * HDIM];
__device__ __align__(16) fp16 g_w1[(size_t)HDIM * 4 * HDIM];
__device__ __align__(16) fp16 g_w2[(size_t)4 * HDIM * HDIM];

#define CP_ASYNC16(dst, src) \
    asm volatile("cp.async.cg.shared.global [%0], [%1], 16;\n" :: "r"(dst), "l"(src))

__device__ __forceinline__ unsigned sptr(const void* p) {
    return (unsigned)__cvta_generic_to_shared(p);
}
__device__ __forceinline__ unsigned packh(float x, float y) {
    fp162 t = __floats2half2_rn(x, y);
    return *(unsigned*)&t;
}

// ---------------- all-weight fp32 -> fp16 (one launch) ----------------
__global__ void f2h_all_kernel(const float* __restrict__ a0, const float* __restrict__ a1,
                               const float* __restrict__ a2, const float* __restrict__ a3,
                               fp16* __restrict__ b0, fp16* __restrict__ b1,
                               fp16* __restrict__ b2, fp16* __restrict__ b3)
{
    const int   n4[4] = {196608, 65536, 262144, 262144};
    const float* src;
    fp16* dst;
    int seg = blockIdx.y;
    if (seg == 0)      { src = a0; dst = b0; }
    else if (seg == 1) { src = a1; dst = b1; }
    else if (seg == 2) { src = a2; dst = b2; }
    else               { src = a3; dst = b3; }
    int i = blockIdx.x * blockDim.x + threadIdx.x;
    if (i >= n4[seg]) return;
    float4 v = *(const float4*)(src + (size_t)i * 4);
    *(fp162*)(dst + (size_t)i * 4)     = __floats2half2_rn(v.x, v.y);
    *(fp162*)(dst + (size_t)i * 4 + 2) = __floats2half2_rn(v.z, v.w);
}

// ---------------- fused roll+partition+LN1: x -> win(f32) + xnb(fp16) -------
__global__ void __launch_bounds__(256) partln_kernel(
    const float* __restrict__ x, float* __restrict__ win, fp16* __restrict__ xnb,
    const float* __restrict__ lw, const float* __restrict__ lb)
{
    extern __shared__ float tile[];     // [512][33]
    int t0 = blockIdx.x * 32;
    int tx = threadIdx.x & 31;
    int ty = threadIdx.x >> 5;

    {
        int t  = t0 + tx;
        int w  = t >> 6;
        int l  = t & 63;
        int hb = w >> 5, wb = w & 31;
        int ii = l >> 3, jj = l & 7;
        int sh = (hb * 8 + ii + 4) & 255;
        int sw = (wb * 8 + jj + 4) & 255;
        int pix = sh * IMG + sw;
#pragma unroll
        for (int cc = 0; cc < 64; cc++) {
            int c = ty + cc * 8;
            tile[c * 33 + tx] = x[(size_t)c * NPIX + pix];
        }
    }
    __syncthreads();

#pragma unroll
    for (int ti = 0; ti < 4; ti++) {
        int tok = ty + ti * 8;
        float v[16];
        float sum = 0.f, sq = 0.f;
#pragma unroll
        for (int j = 0; j < 16; j++) {
            float f = tile[(tx + j * 32) * 33 + tok];
            v[j] = f;
            sum += f;
            sq  += f * f;
        }
#pragma unroll
        for (int o = 16; o; o >>= 1) {
            sum += __shfl_xor_sync(0xffffffffu, sum, o);
            sq  += __shfl_xor_sync(0xffffffffu, sq, o);
        }
        float mu  = sum * (1.f / HDIM);
        float var = sq * (1.f / HDIM) - mu * mu;
        float inv = rsqrtf(var + 1e-5f);

        size_t rowoff = (size_t)(t0 + tok) * HDIM;
#pragma unroll
        for (int j = 0; j < 16; j++) {
            int c = tx + j * 32;
            win[rowoff + c] = v[j];
            float r = (v[j] - mu) * inv * lw[c] + lb[c];
            xnb[rowoff + c] = __float2half(r);
        }
    }
}

// ---------------- window reverse ----------------
__global__ void reverse_kernel(const float* __restrict__ o2, float* __restrict__ out)
{
    __shared__ float tile[32][33];
    int t0 = blockIdx.x * 32;
    int c0 = blockIdx.y * 32;
    int tx = threadIdx.x;
    int ty = threadIdx.y;

#pragma unroll
    for (int cc = 0; cc < 4; cc++) {
        int tt = ty + cc * 8;
        tile[tt][tx] = o2[(size_t)(t0 + tt) * HDIM + c0 + tx];
    }
    __syncthreads();

    int t  = t0 + tx;
    int w  = t >> 6;
    int l  = t & 63;
    int hb = w >> 5, wb = w & 31;
    int ii = l >> 3, jj = l & 7;
    int dh = (hb * 8 + ii + 4) & 255;
    int dw = (wb * 8 + jj + 4) & 255;
    int pix = dh * IMG + dw;

#pragma unroll
    for (int cc = 0; cc < 4; cc++) {
        int c = c0 + ty + cc * 8;
        out[(size_t)c * NPIX + pix] = tile[tx][ty + cc * 8];
    }
}

// ---------------- LayerNorm -> fp16 (for LN2) ----------------
__global__ void ln_kernel(const float* __restrict__ in, fp16* __restrict__ out,
                          const float* __restrict__ w, const float* __restrict__ b)
{
    int warp = (blockIdx.x * blockDim.x + threadIdx.x) >> 5;
    int lane = threadIdx.x & 31;
    if (warp >= NTOK) return;
    const float* row = in + (size_t)warp * HDIM;

    float4 v[4];
    float sum = 0.f, sq = 0.f;
#pragma unroll
    for (int i = 0; i < 4; i++) {
        v[i] = *(const float4*)(row + (size_t)(i * 32 + lane) * 4);
        sum += v[i].x + v[i].y + v[i].z + v[i].w;
        sq  += v[i].x * v[i].x + v[i].y * v[i].y + v[i].z * v[i].z + v[i].w * v[i].w;
    }
#pragma unroll
    for (int o = 16; o; o >>= 1) {
        sum += __shfl_xor_sync(0xffffffffu, sum, o);
        sq  += __shfl_xor_sync(0xffffffffu, sq, o);
    }
    float mu  = sum * (1.f / HDIM);
    float var = sq * (1.f / HDIM) - mu * mu;
    float inv = rsqrtf(var + 1e-5f);

    fp16* orow = out + (size_t)warp * HDIM;
#pragma unroll
    for (int i = 0; i < 4; i++) {
        int c = (i * 32 + lane) * 4;
        float4 wv = *(const float4*)(w + c);
        float4 bv = *(const float4*)(b + c);
        float rx = (v[i].x - mu) * inv * wv.x + bv.x;
        float ry = (v[i].y - mu) * inv * wv.y + bv.y;
        float rz = (v[i].z - mu) * inv * wv.z + bv.z;
        float rw = (v[i].w - mu) * inv * wv.w + bv.w;
        *(fp162*)(orow + c)     = __floats2half2_rn(rx, ry);
        *(fp162*)(orow + c + 2) = __floats2half2_rn(rz, rw);
    }
}

// ---------------- fp16 GEMM: 256x128x32 block, 8 warps (4x2), 64x64 tiles ---
#define GBM 256
#define GBN 128
#define GBK 32
#define ASTRIDE 40            // 32 + 8
#define BSTRIDE 136           // 128 + 8
#define ASZ (GBM * ASTRIDE)   // 10240 elems
#define BSZ (GBK * BSTRIDE)   // 4352 elems
#define GSMEM ((2 * ASZ + 2 * BSZ) * 2)   // 58368 bytes

template <int EPI, typename CT>
__global__ void __launch_bounds__(256) hgemm_kernel(
    const fp16* __restrict__ A, const fp16* __restrict__ B,
    const float* __restrict__ bias, CT* __restrict__ C,
    int M, int N, int K,
    const float* __restrict__ res, const float* __restrict__ gamma)
{
    extern __shared__ fp16 dsm[];
    fp16* As = dsm;                  // [2][256][40]
    fp16* Bs = dsm + 2 * ASZ;        // [2][32][136]

    int tid  = threadIdx.x;
    int lane = tid & 31;
    int warp = tid >> 5;
    int wm = warp >> 1;      // 0..3  (M)
    int wn = warp & 1;       // 0..1  (N)
    int row0 = blockIdx.y * GBM;
    int col0 = blockIdx.x * GBN;

    const fp16* Ab = A + (size_t)row0 * K;
    const fp16* Bb = B + col0;

    // f16 accumulators: 2 regs per 16x8 tile, 4x8 tiles
    unsigned acc[4][8][2];
#pragma unroll
    for (int mi = 0; mi < 4; mi++)
#pragma unroll
        for (int ni = 0; ni < 8; ni++) {
            acc[mi][ni][0] = 0u;
            acc[mi][ni][1] = 0u;
        }

    // A: 256 rows x 32 elems = 1024 chunks -> 4/thread (r = ch>>2, c = (ch&3)*8)
    // B: 32 rows x 128 elems = 512 chunks  -> 2/thread (r = ch>>4, c = (ch&15)*8)
#define LOAD_TILE(buf, k0)                                                       \
    do {                                                                         \
        _Pragma("unroll")                                                        \
        for (int i = 0; i < 4; i++) {                                            \
            int ch = tid + i * 256;                                              \
            int r = ch >> 2, c = (ch & 3) * 8;                                   \
            CP_ASYNC16(sptr(&As[(buf) * ASZ + r * ASTRIDE + c]),                 \
                       Ab + (size_t)r * K + (k0) + c);                           \
        }                                                                        \
        _Pragma("unroll")                                                        \
        for (int i = 0; i < 2; i++) {                                            \
            int ch = tid + i * 256;                                              \
            int r = ch >> 4, c = (ch & 15) * 8;                                  \
            CP_ASYNC16(sptr(&Bs[(buf) * BSZ + r * BSTRIDE + c]),                 \
                       Bb + (size_t)((k0) + r) * N + c);                         \
        }                                                                        \
        asm volatile("cp.async.commit_group;\n" ::: "memory");                   \
    } while (0)

    int nk = K / GBK;
    LOAD_TILE(0, 0);

    for (int kt = 0; kt < nk; kt++) {
        asm volatile("cp.async.wait_group 0;\n" ::: "memory");
        __syncthreads();
        int cur = kt & 1;
        if (kt + 1 < nk) LOAD_TILE(cur ^ 1, (kt + 1) * GBK);

#pragma unroll
        for (int kk = 0; kk < 2; kk++) {
            unsigned a[4][4], b[8][2];
#pragma unroll
            for (int mi = 0; mi < 4; mi++) {
                unsigned addr = sptr(&As[cur * ASZ
                    + (wm * 64 + mi * 16 + (lane & 15)) * ASTRIDE
                    + kk * 16 + (lane >> 4) * 8]);
                asm volatile("ldmatrix.sync.aligned.m8n8.x4.shared.b16 {%0,%1,%2,%3},[%4];"
                    : "=r"(a[mi][0]), "=r"(a[mi][1]), "=r"(a[mi][2]), "=r"(a[mi][3])
                    : "r"(addr));
            }
#pragma unroll
            for (int ni = 0; ni < 8; ni++) {
                unsigned addr = sptr(&Bs[cur * BSZ
                    + (kk * 16 + (lane & 15)) * BSTRIDE + wn * 64 + ni * 8]);
                asm volatile("ldmatrix.sync.aligned.m8n8.x2.trans.shared.b16 {%0,%1},[%2];"
                    : "=r"(b[ni][0]), "=r"(b[ni][1]) : "r"(addr));
            }
#pragma unroll
            for (int mi = 0; mi < 4; mi++)
#pragma unroll
                for (int ni = 0; ni < 8; ni++)
                    asm volatile("mma.sync.aligned.m16n8k16.row.col.f16.f16.f16.f16 "
                        "{%0,%1},{%2,%3,%4,%5},{%6,%7},{%0,%1};"
                        : "+r"(acc[mi][ni][0]), "+r"(acc[mi][ni][1])
                        : "r"(a[mi][0]), "r"(a[mi][1]), "r"(a[mi][2]), "r"(a[mi][3]),
                          "r"(b[ni][0]), "r"(b[ni][1]));
        }
    }

    int lr = lane >> 2;
    int lc = (lane & 3) * 2;
#pragma unroll
    for (int mi = 0; mi < 4; mi++) {
#pragma unroll
        for (int half = 0; half < 2; half++) {
            int grow = row0 + wm * 64 + mi * 16 + lr + half * 8;
#pragma unroll
            for (int ni = 0; ni < 8; ni++) {
                int gcol = col0 + wn * 64 + ni * 8 + lc;
                fp162 hv = *(fp162*)&acc[mi][ni][half];
                float v0 = __low2float(hv)  + bias[gcol];
                float v1 = __high2float(hv) + bias[gcol + 1];
                if (EPI == 1) {
                    v0 = 0.5f * v0 * (1.f + erff(v0 * 0.70710678118f));
                    v1 = 0.5f * v1 * (1.f + erff(v1 * 0.70710678118f));
                }
                if (EPI == 2) {
                    const float* rp = res + (size_t)grow * N + gcol;
                    v0 = rp[0] + gamma[gcol] * v0;
                    v1 = rp[1] + gamma[gcol + 1] * v1;
                }
                if (sizeof(CT) == 4) {
                    float* cp = (float*)C + (size_t)grow * N + gcol;
                    cp[0] = v0; cp[1] = v1;
                } else {
                    fp16* cp = (fp16*)C + (size_t)grow * N + gcol;
                    *(fp162*)cp = __floats2half2_rn(v0, v1);
                }
            }
        }
    }
}

// ---------------- tensor-core attention (fp16 in, f32 accum) ----------------
__global__ void __launch_bounds__(128) attn_mma_kernel(
    const fp16* __restrict__ qkv, const float* __restrict__ rel_table,
    fp16* __restrict__ out)
{
    __shared__ fp16 qs[64][72], ks[64][72], vs[64][72];
    __shared__ float tbl[2][225];
    __shared__ int rg[64];

    int w    = blockIdx.x;
    int hb   = blockIdx.y;
    int tid  = threadIdx.x;
    int lane = tid & 31;
    int warp = tid >> 5;
    int hh   = warp >> 1;
    int wr   = warp & 1;

    for (int i = tid; i < 2 * 225; i += 128) {
        int h2 = i / 225, idx = i - h2 * 225;
        tbl[h2][idx] = rel_table[idx * HEADS + hb * 2 + h2];
    }
    if (tid < 64) {
        int hbw = w >> 5, wbw = w & 31;
        int ii = hbw * 8 + (tid >> 3);
        int jj = wbw * 8 + (tid & 7);
        int rh = (ii < 248) ? 0 : (ii < 252 ? 1 : 2);
        int rw = (jj < 248) ? 0 : (jj < 252 ? 1 : 2);
        rg[tid] = rh * 3 + rw;
    }

    const fp16* base = qkv + (size_t)w * 64 * (3 * HDIM) + hb * 64;
    for (int ch = tid; ch < 512; ch += 128) {
        int r = ch >> 3, c = (ch & 7) * 8;
        const fp16* rp = base + (size_t)r * (3 * HDIM);
        CP_ASYNC16(sptr(&qs[r][c]), rp + c);
        CP_ASYNC16(sptr(&ks[r][c]), rp + HDIM + c);
        CP_ASYNC16(sptr(&vs[r][c]), rp + 2 * HDIM + c);
    }
    asm volatile("cp.async.commit_group;\n" ::: "memory");
    asm volatile("cp.async.wait_group 0;\n" ::: "memory");
    __syncthreads();

    int co = hh * 32;

    float sacc[2][8][4];
#pragma unroll
    for (int mi = 0; mi < 2; mi++)
#pragma unroll
        for (int ni = 0; ni < 8; ni++)
#pragma unroll
            for (int r = 0; r < 4; r++) sacc[mi][ni][r] = 0.f;

#pragma unroll
    for (int kk = 0; kk < 2; kk++) {
        int k0 = co + kk * 16;
        unsigned af[2][4];
#pragma unroll
        for (int mi = 0; mi < 2; mi++) {
            unsigned addr = sptr(&qs[wr * 32 + mi * 16 + (lane & 15)][k0 + (lane >> 4) * 8]);
            asm volatile("ldmatrix.sync.aligned.m8n8.x4.shared.b16 {%0,%1,%2,%3},[%4];"
                : "=r"(af[mi][0]), "=r"(af[mi][1]), "=r"(af[mi][2]), "=r"(af[mi][3])
                : "r"(addr));
        }
        unsigned bf[8][2];
#pragma unroll
        for (int ni = 0; ni < 8; ni++) {
            unsigned addr = sptr(&ks[ni * 8 + (lane & 7)][k0 + ((lane >> 3) & 1) * 8]);
            asm volatile("ldmatrix.sync.aligned.m8n8.x2.shared.b16 {%0,%1},[%2];"
                : "=r"(bf[ni][0]), "=r"(bf[ni][1]) : "r"(addr));
        }
#pragma unroll
        for (int mi = 0; mi < 2; mi++)
#pragma unroll
            for (int ni = 0; ni < 8; ni++)
                asm volatile("mma.sync.aligned.m16n8k16.row.col.f32.f16.f16.f32 "
                    "{%0,%1,%2,%3},{%4,%5,%6,%7},{%8,%9},{%0,%1,%2,%3};"
                    : "+f"(sacc[mi][ni][0]), "+f"(sacc[mi][ni][1]),
                      "+f"(sacc[mi][ni][2]), "+f"(sacc[mi][ni][3])
                    : "r"(af[mi][0]), "r"(af[mi][1]), "r"(af[mi][2]), "r"(af[mi][3]),
                      "r"(bf[ni][0]), "r"(bf[ni][1]));
    }

    const float scale = 0.17677669529663687f;
    int lq  = lane >> 2;
    int lc2 = (lane & 3) * 2;
#pragma unroll
    for (int mi = 0; mi < 2; mi++) {
#pragma unroll
        for (int hf = 0; hf < 2; hf++) {
            int l = wr * 32 + mi * 16 + hf * 8 + lq;
            int il = l >> 3, jl = l & 7;
            int rgl = rg[l];
            float mx = -1e30f;
#pragma unroll
            for (int ni = 0; ni < 8; ni++) {
#pragma unroll
                for (int j = 0; j < 2; j++) {
                    int m = ni * 8 + lc2 + j;
                    int im = m >> 3, jm = m & 7;
                    float v = sacc[mi][ni][hf * 2 + j] * scale
                            + tbl[hh][(il - im + 7) * 15 + (jl - jm + 7)];
                    if (rg[m] != rgl) v = -1e30f;
                    sacc[mi][ni][hf * 2 + j] = v;
                    mx = fmaxf(mx, v);
                }
            }
            mx = fmaxf(mx, __shfl_xor_sync(0xffffffffu, mx, 1));
            mx = fmaxf(mx, __shfl_xor_sync(0xffffffffu, mx, 2));
            float sum = 0.f;
#pragma unroll
            for (int ni = 0; ni < 8; ni++) {
#pragma unroll
                for (int j = 0; j < 2; j++) {
                    float e = __expf(sacc[mi][ni][hf * 2 + j] - mx);
                    sacc[mi][ni][hf * 2 + j] = e;
                    sum += e;
                }
            }
            sum += __shfl_xor_sync(0xffffffffu, sum, 1);
            sum += __shfl_xor_sync(0xffffffffu, sum, 2);
            float inv = 1.f / sum;
#pragma unroll
            for (int ni = 0; ni < 8; ni++) {
                sacc[mi][ni][hf * 2 + 0] *= inv;
                sacc[mi][ni][hf * 2 + 1] *= inv;
            }
        }
    }

    unsigned pfr[2][4][4];
#pragma unroll
    for (int mi = 0; mi < 2; mi++)
#pragma unroll
        for (int q = 0; q < 4; q++) {
            pfr[mi][q][0] = packh(sacc[mi][2 * q][0],     sacc[mi][2 * q][1]);
            pfr[mi][q][1] = packh(sacc[mi][2 * q][2],     sacc[mi][2 * q][3]);
            pfr[mi][q][2] = packh(sacc[mi][2 * q + 1][0], sacc[mi][2 * q + 1][1]);
            pfr[mi][q][3] = packh(sacc[mi][2 * q + 1][2], sacc[mi][2 * q + 1][3]);
        }

    float oacc[2][4][4];
#pragma unroll
    for (int mi = 0; mi < 2; mi++)
#pragma unroll
        for (int nj = 0; nj < 4; nj++)
#pragma unroll
            for (int r = 0; r < 4; r++) oacc[mi][nj][r] = 0.f;

#pragma unroll
    for (int q = 0; q < 4; q++) {
        unsigned bv[4][2];
#pragma unroll
        for (int nj = 0; nj < 4; nj++) {
            unsigned addr = sptr(&vs[q * 16 + (lane & 15)][co + nj * 8]);
            asm volatile("ldmatrix.sync.aligned.m8n8.x2.trans.shared.b16 {%0,%1},[%2];"
                : "=r"(bv[nj][0]), "=r"(bv[nj][1]) : "r"(addr));
        }
#pragma unroll
        for (int mi = 0; mi < 2; mi++)
#pragma unroll
            for (int nj = 0; nj < 4; nj++)
                asm volatile("mma.sync.aligned.m16n8k16.row.col.f32.f16.f16.f32 "
                    "{%0,%1,%2,%3},{%4,%5,%6,%7},{%8,%9},{%0,%1,%2,%3};"
                    : "+f"(oacc[mi][nj][0]), "+f"(oacc[mi][nj][1]),
                      "+f"(oacc[mi][nj][2]), "+f"(oacc[mi][nj][3])
                    : "r"(pfr[mi][q][0]), "r"(pfr[mi][q][1]), "r"(pfr[mi][q][2]), "r"(pfr[mi][q][3]),
                      "r"(bv[nj][0]), "r"(bv[nj][1]));
    }

    int hgl = hb * 2 + hh;
#pragma unroll
    for (int mi = 0; mi < 2; mi++)
#pragma unroll
        for (int hf = 0; hf < 2; hf++) {
            int l = wr * 32 + mi * 16 + hf * 8 + lq;
            fp16* op = out + (size_t)(w * 64 + l) * HDIM + hgl * 32 + lc2;
#pragma unroll
            for (int nj = 0; nj < 4; nj++)
                *(fp162*)(op + nj * 8) =
                    __floats2half2_rn(oacc[mi][nj][hf * 2 + 0], oacc[mi][nj][hf * 2 + 1]);
        }
}

// ---------------- launch -----------------------------------------------------
extern "C" void kernel_launch(void* const* d_in, const int* in_sizes, int n_in,
                              void* d_out, int out_size)
{
    (void)in_sizes; (void)n_in; (void)out_size;
    const float* x     = (const float*)d_in[0];
    const float* n1w   = (const float*)d_in[1];
    const float* n1b   = (const float*)d_in[2];
    const float* qkvw  = (const float*)d_in[3];
    const float* qkvb  = (const float*)d_in[4];
    const float* projw = (const float*)d_in[5];
    const float* projb = (const float*)d_in[6];
    const float* relt  = (const float*)d_in[7];
    const float* g1    = (const float*)d_in[8];
    const float* n2w   = (const float*)d_in[9];
    const float* n2b   = (const float*)d_in[10];
    const float* fc1w  = (const float*)d_in[11];
    const float* fc1b  = (const float*)d_in[12];
    const float* fc2w  = (const float*)d_in[13];
    const float* fc2b  = (const float*)d_in[14];
    const float* g2    = (const float*)d_in[15];
    float* out = (float*)d_out;

    float *p_win, *p_o1;
    fp16 *p_xnb, *p_qkvb, *p_attb, *p_hb, *p_wq, *p_wp, *p_w1, *p_w2;
    cudaGetSymbolAddress((void**)&p_win,  g_win);
    cudaGetSymbolAddress((void**)&p_o1,   g_o1);
    cudaGetSymbolAddress((void**)&p_xnb,  g_xnb);
    cudaGetSymbolAddress((void**)&p_qkvb, g_qkvb);
    cudaGetSymbolAddress((void**)&p_attb, g_attb);
    cudaGetSymbolAddress((void**)&p_hb,   g_hb);
    cudaGetSymbolAddress((void**)&p_wq,   g_wq);
    cudaGetSymbolAddress((void**)&p_wp,   g_wp);
    cudaGetSymbolAddress((void**)&p_w1,   g_w1);
    cudaGetSymbolAddress((void**)&p_w2,   g_w2);

    cudaFuncSetAttribute(hgemm_kernel<0, fp16>,
        cudaFuncAttributeMaxDynamicSharedMemorySize, GSMEM);
    cudaFuncSetAttribute(hgemm_kernel<1, fp16>,
        cudaFuncAttributeMaxDynamicSharedMemorySize, GSMEM);
    cudaFuncSetAttribute(hgemm_kernel<2, float>,
        cudaFuncAttributeMaxDynamicSharedMemorySize, GSMEM);
    cudaFuncSetAttribute(partln_kernel,
        cudaFuncAttributeMaxDynamicSharedMemorySize, 512 * 33 * 4);

    f2h_all_kernel<<<dim3(1024, 4), 256>>>(qkvw, projw, fc1w, fc2w,
                                           p_wq, p_wp, p_w1, p_w2);

    partln_kernel<<<NTOK / 32, 256, 512 * 33 * 4>>>(x, p_win, p_xnb, n1w, n1b);

    hgemm_kernel<0, fp16><<<dim3(3 * HDIM / GBN, NTOK / GBM), 256, GSMEM>>>(
        p_xnb, p_wq, qkvb, p_qkvb, NTOK, 3 * HDIM, HDIM, nullptr, nullptr);
    attn_mma_kernel<<<dim3(NW, 8), 128>>>(p_qkvb, relt, p_attb);
    hgemm_kernel<2, float><<<dim3(HDIM / GBN, NTOK / GBM), 256, GSMEM>>>(
        p_attb, p_wp, projb, p_o1, NTOK, HDIM, HDIM, p_win, g1);
    ln_kernel<<<NTOK / 8, 256>>>(p_o1, p_xnb, n2w, n2b);
    hgemm_kernel<1, fp16><<<dim3(4 * HDIM / GBN, NTOK / GBM), 256, GSMEM>>>(
        p_xnb, p_w1, fc1b, p_hb, NTOK, 4 * HDIM, HDIM, nullptr, nullptr);
    hgemm_kernel<2, float><<<dim3(HDIM / GBN, NTOK / GBM), 256, GSMEM>>>(
        p_hb, p_w2, fc2b, p_win, NTOK, HDIM, 4 * HDIM, p_o1, g2);

    dim3 tp(32, 8);
    reverse_kernel<<<dim3(NTOK / 32, HDIM / 32), tp>>>(p_win, out);
}

// round 17
// speedup vs baseline: 1.0322x; 1.0322x over previous
#include <cuda_runtime.h>
#include <cuda_fp16.h>
#include <stdint.h>
#include <math.h>

// ---------------- problem constants ----------------
#define HDIM   512
#define HEADS  16
#define HD     32
#define WS     8
#define L      64
#define NW     1024
#define NTOK   65536
#define IMG    256
#define NPIX   65536

typedef __half  fp16;
typedef __half2 fp162;

// ---------------- scratch ----------------
__device__ float g_win[(size_t)NTOK * HDIM];
__device__ float g_o1[(size_t)NTOK * HDIM];
__device__ __align__(16) fp16 g_xnb[(size_t)NTOK * HDIM];
__device__ __align__(16) fp16 g_qkvb[(size_t)NTOK * 3 * HDIM];
__device__ __align__(16) fp16 g_attb[(size_t)NTOK * HDIM];
__device__ __align__(16) fp16 g_hb[(size_t)NTOK * 4 * HDIM];
__device__ __align__(16) fp16 g_wq[(size_t)HDIM * 3 * HDIM];
__device__ __align__(16) fp16 g_wp[(size_t)HDIM * HDIM];
__device__ __align__(16) fp16 g_w1[(size_t)HDIM * 4 * HDIM];
__device__ __align__(16) fp16 g_w2[(size_t)4 * HDIM * HDIM];

#define CP_ASYNC16(dst, src) \
    asm volatile("cp.async.cg.shared.global [%0], [%1], 16;\n" :: "r"(dst), "l"(src))

__device__ __forceinline__ unsigned sptr(const void* p) {
    return (unsigned)__cvta_generic_to_shared(p);
}
__device__ __forceinline__ unsigned packh(float x, float y) {
    fp162 t = __floats2half2_rn(x, y);
    return *(unsigned*)&t;
}

// ---------------- all-weight fp32 -> fp16 (one launch) ----------------
__global__ void f2h_all_kernel(const float* __restrict__ a0, const float* __restrict__ a1,
                               const float* __restrict__ a2, const float* __restrict__ a3,
                               fp16* __restrict__ b0, fp16* __restrict__ b1,
                               fp16* __restrict__ b2, fp16* __restrict__ b3)
{
    const int   n4[4] = {196608, 65536, 262144, 262144};
    const float* src;
    fp16* dst;
    int seg = blockIdx.y;
    if (seg == 0)      { src = a0; dst = b0; }
    else if (seg == 1) { src = a1; dst = b1; }
    else if (seg == 2) { src = a2; dst = b2; }
    else               { src = a3; dst = b3; }
    int i = blockIdx.x * blockDim.x + threadIdx.x;
    if (i >= n4[seg]) return;
    float4 v = *(const float4*)(src + (size_t)i * 4);
    *(fp162*)(dst + (size_t)i * 4)     = __floats2half2_rn(v.x, v.y);
    *(fp162*)(dst + (size_t)i * 4 + 2) = __floats2half2_rn(v.z, v.w);
}

// ---------------- fused roll+partition+LN1: x -> win(f32) + xnb(fp16) -------
__global__ void __launch_bounds__(256) partln_kernel(
    const float* __restrict__ x, float* __restrict__ win, fp16* __restrict__ xnb,
    const float* __restrict__ lw, const float* __restrict__ lb)
{
    extern __shared__ float tile[];     // [512][33]
    int t0 = blockIdx.x * 32;
    int tx = threadIdx.x & 31;
    int ty = threadIdx.x >> 5;

    {
        int t  = t0 + tx;
        int w  = t >> 6;
        int l  = t & 63;
        int hb = w >> 5, wb = w & 31;
        int ii = l >> 3, jj = l & 7;
        int sh = (hb * 8 + ii + 4) & 255;
        int sw = (wb * 8 + jj + 4) & 255;
        int pix = sh * IMG + sw;
#pragma unroll
        for (int cc = 0; cc < 64; cc++) {
            int c = ty + cc * 8;
            tile[c * 33 + tx] = x[(size_t)c * NPIX + pix];
        }
    }
    __syncthreads();

#pragma unroll
    for (int ti = 0; ti < 4; ti++) {
        int tok = ty + ti * 8;
        float v[16];
        float sum = 0.f, sq = 0.f;
#pragma unroll
        for (int j = 0; j < 16; j++) {
            float f = tile[(tx + j * 32) * 33 + tok];
            v[j] = f;
            sum += f;
            sq  += f * f;
        }
#pragma unroll
        for (int o = 16; o; o >>= 1) {
            sum += __shfl_xor_sync(0xffffffffu, sum, o);
            sq  += __shfl_xor_sync(0xffffffffu, sq, o);
        }
        float mu  = sum * (1.f / HDIM);
        float var = sq * (1.f / HDIM) - mu * mu;
        float inv = rsqrtf(var + 1e-5f);

        size_t rowoff = (size_t)(t0 + tok) * HDIM;
#pragma unroll
        for (int j = 0; j < 16; j++) {
            int c = tx + j * 32;
            win[rowoff + c] = v[j];
            float r = (v[j] - mu) * inv * lw[c] + lb[c];
            xnb[rowoff + c] = __float2half(r);
        }
    }
}

// ---------------- window reverse ----------------
__global__ void reverse_kernel(const float* __restrict__ o2, float* __restrict__ out)
{
    __shared__ float tile[32][33];
    int t0 = blockIdx.x * 32;
    int c0 = blockIdx.y * 32;
    int tx = threadIdx.x;
    int ty = threadIdx.y;

#pragma unroll
    for (int cc = 0; cc < 4; cc++) {
        int tt = ty + cc * 8;
        tile[tt][tx] = o2[(size_t)(t0 + tt) * HDIM + c0 + tx];
    }
    __syncthreads();

    int t  = t0 + tx;
    int w  = t >> 6;
    int l  = t & 63;
    int hb = w >> 5, wb = w & 31;
    int ii = l >> 3, jj = l & 7;
    int dh = (hb * 8 + ii + 4) & 255;
    int dw = (wb * 8 + jj + 4) & 255;
    int pix = dh * IMG + dw;

#pragma unroll
    for (int cc = 0; cc < 4; cc++) {
        int c = c0 + ty + cc * 8;
        out[(size_t)c * NPIX + pix] = tile[tx][ty + cc * 8];
    }
}

// ---------------- LayerNorm -> fp16 (for LN2) ----------------
__global__ void ln_kernel(const float* __restrict__ in, fp16* __restrict__ out,
                          const float* __restrict__ w, const float* __restrict__ b)
{
    int warp = (blockIdx.x * blockDim.x + threadIdx.x) >> 5;
    int lane = threadIdx.x & 31;
    if (warp >= NTOK) return;
    const float* row = in + (size_t)warp * HDIM;

    float4 v[4];
    float sum = 0.f, sq = 0.f;
#pragma unroll
    for (int i = 0; i < 4; i++) {
        v[i] = *(const float4*)(row + (size_t)(i * 32 + lane) * 4);
        sum += v[i].x + v[i].y + v[i].z + v[i].w;
        sq  += v[i].x * v[i].x + v[i].y * v[i].y + v[i].z * v[i].z + v[i].w * v[i].w;
    }
#pragma unroll
    for (int o = 16; o; o >>= 1) {
        sum += __shfl_xor_sync(0xffffffffu, sum, o);
        sq  += __shfl_xor_sync(0xffffffffu, sq, o);
    }
    float mu  = sum * (1.f / HDIM);
    float var = sq * (1.f / HDIM) - mu * mu;
    float inv = rsqrtf(var + 1e-5f);

    fp16* orow = out + (size_t)warp * HDIM;
#pragma unroll
    for (int i = 0; i < 4; i++) {
        int c = (i * 32 + lane) * 4;
        float4 wv = *(const float4*)(w + c);
        float4 bv = *(const float4*)(b + c);
        float rx = (v[i].x - mu) * inv * wv.x + bv.x;
        float ry = (v[i].y - mu) * inv * wv.y + bv.y;
        float rz = (v[i].z - mu) * inv * wv.z + bv.z;
        float rw = (v[i].w - mu) * inv * wv.w + bv.w;
        *(fp162*)(orow + c)     = __floats2half2_rn(rx, ry);
        *(fp162*)(orow + c + 2) = __floats2half2_rn(rz, rw);
    }
}

// ---------------- fp16 GEMM (R11 config: 128x128x64, 8 warps 64x32, f16 acc)
#define GBM 128
#define GBN 128
#define GBK 64
#define ASTRIDE 72
#define BSTRIDE 136
#define ASZ (GBM * ASTRIDE)
#define BSZ (GBK * BSTRIDE)
#define GSMEM ((2 * ASZ + 2 * BSZ) * 2)   // 71680 bytes

template <int EPI, typename CT>
__global__ void __launch_bounds__(256) hgemm_kernel(
    const fp16* __restrict__ A, const fp16* __restrict__ B,
    const float* __restrict__ bias, CT* __restrict__ C,
    int M, int N, int K,
    const float* __restrict__ res, const float* __restrict__ gamma)
{
    extern __shared__ fp16 dsm[];
    fp16* As = dsm;                  // [2][128][72]
    fp16* Bs = dsm + 2 * ASZ;        // [2][64][136]

    int tid  = threadIdx.x;
    int lane = tid & 31;
    int warp = tid >> 5;
    int wm = warp >> 2;
    int wn = warp & 3;
    int row0 = blockIdx.y * GBM;
    int col0 = blockIdx.x * GBN;

    const fp16* Ab = A + (size_t)row0 * K;
    const fp16* Bb = B + col0;

    unsigned acc[4][4][2];
#pragma unroll
    for (int mi = 0; mi < 4; mi++)
#pragma unroll
        for (int ni = 0; ni < 4; ni++) {
            acc[mi][ni][0] = 0u;
            acc[mi][ni][1] = 0u;
        }

#define LOAD_TILE(buf, k0)                                                       \
    do {                                                                         \
        _Pragma("unroll")                                                        \
        for (int i = 0; i < 4; i++) {                                            \
            int ch = tid + i * 256;                                              \
            int r = ch >> 3, c = (ch & 7) * 8;                                   \
            CP_ASYNC16(sptr(&As[(buf) * ASZ + r * ASTRIDE + c]),                 \
                       Ab + (size_t)r * K + (k0) + c);                           \
        }                                                                        \
        _Pragma("unroll")                                                        \
        for (int i = 0; i < 4; i++) {                                            \
            int ch = tid + i * 256;                                              \
            int r = ch >> 4, c = (ch & 15) * 8;                                  \
            CP_ASYNC16(sptr(&Bs[(buf) * BSZ + r * BSTRIDE + c]),                 \
                       Bb + (size_t)((k0) + r) * N + c);                         \
        }                                                                        \
        asm volatile("cp.async.commit_group;\n" ::: "memory");                   \
    } while (0)

    int nk = K / GBK;
    LOAD_TILE(0, 0);

    for (int kt = 0; kt < nk; kt++) {
        asm volatile("cp.async.wait_group 0;\n" ::: "memory");
        __syncthreads();
        int cur = kt & 1;
        if (kt + 1 < nk) LOAD_TILE(cur ^ 1, (kt + 1) * GBK);

#pragma unroll
        for (int kk = 0; kk < 4; kk++) {
            unsigned a[4][4], b[4][2];
#pragma unroll
            for (int mi = 0; mi < 4; mi++) {
                unsigned addr = sptr(&As[cur * ASZ
                    + (wm * 64 + mi * 16 + (lane & 15)) * ASTRIDE
                    + kk * 16 + (lane >> 4) * 8]);
                asm volatile("ldmatrix.sync.aligned.m8n8.x4.shared.b16 {%0,%1,%2,%3},[%4];"
                    : "=r"(a[mi][0]), "=r"(a[mi][1]), "=r"(a[mi][2]), "=r"(a[mi][3])
                    : "r"(addr));
            }
#pragma unroll
            for (int ni = 0; ni < 4; ni++) {
                unsigned addr = sptr(&Bs[cur * BSZ
                    + (kk * 16 + (lane & 15)) * BSTRIDE + wn * 32 + ni * 8]);
                asm volatile("ldmatrix.sync.aligned.m8n8.x2.trans.shared.b16 {%0,%1},[%2];"
                    : "=r"(b[ni][0]), "=r"(b[ni][1]) : "r"(addr));
            }
#pragma unroll
            for (int mi = 0; mi < 4; mi++)
#pragma unroll
                for (int ni = 0; ni < 4; ni++)
                    asm volatile("mma.sync.aligned.m16n8k16.row.col.f16.f16.f16.f16 "
                        "{%0,%1},{%2,%3,%4,%5},{%6,%7},{%0,%1};"
                        : "+r"(acc[mi][ni][0]), "+r"(acc[mi][ni][1])
                        : "r"(a[mi][0]), "r"(a[mi][1]), "r"(a[mi][2]), "r"(a[mi][3]),
                          "r"(b[ni][0]), "r"(b[ni][1]));
        }
    }

    int lr = lane >> 2;
    int lc = (lane & 3) * 2;
#pragma unroll
    for (int mi = 0; mi < 4; mi++) {
#pragma unroll
        for (int half = 0; half < 2; half++) {
            int grow = row0 + wm * 64 + mi * 16 + lr + half * 8;
#pragma unroll
            for (int ni = 0; ni < 4; ni++) {
                int gcol = col0 + wn * 32 + ni * 8 + lc;
                fp162 hv = *(fp162*)&acc[mi][ni][half];
                float v0 = __low2float(hv)  + bias[gcol];
                float v1 = __high2float(hv) + bias[gcol + 1];
                if (EPI == 1) {
                    v0 = 0.5f * v0 * (1.f + erff(v0 * 0.70710678118f));
                    v1 = 0.5f * v1 * (1.f + erff(v1 * 0.70710678118f));
                }
                if (EPI == 2) {
                    const float* rp = res + (size_t)grow * N + gcol;
                    v0 = rp[0] + gamma[gcol] * v0;
                    v1 = rp[1] + gamma[gcol + 1] * v1;
                }
                if (sizeof(CT) == 4) {
                    float* cp = (float*)C + (size_t)grow * N + gcol;
                    cp[0] = v0; cp[1] = v1;
                } else {
                    fp16* cp = (fp16*)C + (size_t)grow * N + gcol;
                    *(fp162*)cp = __floats2half2_rn(v0, v1);
                }
            }
        }
    }
}

// ---------------- tensor-core attention (fp16 in, f32 accum) ----------------
__global__ void __launch_bounds__(128) attn_mma_kernel(
    const fp16* __restrict__ qkv, const float* __restrict__ rel_table,
    fp16* __restrict__ out)
{
    __shared__ fp16 qs[64][72], ks[64][72], vs[64][72];
    __shared__ float tbl[2][225];
    __shared__ int rg[64];

    int w    = blockIdx.x;
    int hb   = blockIdx.y;
    int tid  = threadIdx.x;
    int lane = tid & 31;
    int warp = tid >> 5;
    int hh   = warp >> 1;
    int wr   = warp & 1;

    for (int i = tid; i < 2 * 225; i += 128) {
        int h2 = i / 225, idx = i - h2 * 225;
        tbl[h2][idx] = rel_table[idx * HEADS + hb * 2 + h2];
    }
    if (tid < 64) {
        int hbw = w >> 5, wbw = w & 31;
        int ii = hbw * 8 + (tid >> 3);
        int jj = wbw * 8 + (tid & 7);
        int rh = (ii < 248) ? 0 : (ii < 252 ? 1 : 2);
        int rw = (jj < 248) ? 0 : (jj < 252 ? 1 : 2);
        rg[tid] = rh * 3 + rw;
    }

    const fp16* base = qkv + (size_t)w * 64 * (3 * HDIM) + hb * 64;
    for (int ch = tid; ch < 512; ch += 128) {
        int r = ch >> 3, c = (ch & 7) * 8;
        const fp16* rp = base + (size_t)r * (3 * HDIM);
        CP_ASYNC16(sptr(&qs[r][c]), rp + c);
        CP_ASYNC16(sptr(&ks[r][c]), rp + HDIM + c);
        CP_ASYNC16(sptr(&vs[r][c]), rp + 2 * HDIM + c);
    }
    asm volatile("cp.async.commit_group;\n" ::: "memory");
    asm volatile("cp.async.wait_group 0;\n" ::: "memory");
    __syncthreads();

    int co = hh * 32;

    float sacc[2][8][4];
#pragma unroll
    for (int mi = 0; mi < 2; mi++)
#pragma unroll
        for (int ni = 0; ni < 8; ni++)
#pragma unroll
            for (int r = 0; r < 4; r++) sacc[mi][ni][r] = 0.f;

#pragma unroll
    for (int kk = 0; kk < 2; kk++) {
        int k0 = co + kk * 16;
        unsigned af[2][4];
#pragma unroll
        for (int mi = 0; mi < 2; mi++) {
            unsigned addr = sptr(&qs[wr * 32 + mi * 16 + (lane & 15)][k0 + (lane >> 4) * 8]);
            asm volatile("ldmatrix.sync.aligned.m8n8.x4.shared.b16 {%0,%1,%2,%3},[%4];"
                : "=r"(af[mi][0]), "=r"(af[mi][1]), "=r"(af[mi][2]), "=r"(af[mi][3])
                : "r"(addr));
        }
        unsigned bf[8][2];
#pragma unroll
        for (int ni = 0; ni < 8; ni++) {
            unsigned addr = sptr(&ks[ni * 8 + (lane & 7)][k0 + ((lane >> 3) & 1) * 8]);
            asm volatile("ldmatrix.sync.aligned.m8n8.x2.shared.b16 {%0,%1},[%2];"
                : "=r"(bf[ni][0]), "=r"(bf[ni][1]) : "r"(addr));
        }
#pragma unroll
        for (int mi = 0; mi < 2; mi++)
#pragma unroll
            for (int ni = 0; ni < 8; ni++)
                asm volatile("mma.sync.aligned.m16n8k16.row.col.f32.f16.f16.f32 "
                    "{%0,%1,%2,%3},{%4,%5,%6,%7},{%8,%9},{%0,%1,%2,%3};"
                    : "+f"(sacc[mi][ni][0]), "+f"(sacc[mi][ni][1]),
                      "+f"(sacc[mi][ni][2]), "+f"(sacc[mi][ni][3])
                    : "r"(af[mi][0]), "r"(af[mi][1]), "r"(af[mi][2]), "r"(af[mi][3]),
                      "r"(bf[ni][0]), "r"(bf[ni][1]));
    }

    const float scale = 0.17677669529663687f;
    int lq  = lane >> 2;
    int lc2 = (lane & 3) * 2;
#pragma unroll
    for (int mi = 0; mi < 2; mi++) {
#pragma unroll
        for (int hf = 0; hf < 2; hf++) {
            int l = wr * 32 + mi * 16 + hf * 8 + lq;
            int il = l >> 3, jl = l & 7;
            int rgl = rg[l];
            float mx = -1e30f;
#pragma unroll
            for (int ni = 0; ni < 8; ni++) {
#pragma unroll
                for (int j = 0; j < 2; j++) {
                    int m = ni * 8 + lc2 + j;
                    int im = m >> 3, jm = m & 7;
                    float v = sacc[mi][ni][hf * 2 + j] * scale
                            + tbl[hh][(il - im + 7) * 15 + (jl - jm + 7)];
                    if (rg[m] != rgl) v = -1e30f;
                    sacc[mi][ni][hf * 2 + j] = v;
                    mx = fmaxf(mx, v);
                }
            }
            mx = fmaxf(mx, __shfl_xor_sync(0xffffffffu, mx, 1));
            mx = fmaxf(mx, __shfl_xor_sync(0xffffffffu, mx, 2));
            float sum = 0.f;
#pragma unroll
            for (int ni = 0; ni < 8; ni++) {
#pragma unroll
                for (int j = 0; j < 2; j++) {
                    float e = __expf(sacc[mi][ni][hf * 2 + j] - mx);
                    sacc[mi][ni][hf * 2 + j] = e;
                    sum += e;
                }
            }
            sum += __shfl_xor_sync(0xffffffffu, sum, 1);
            sum += __shfl_xor_sync(0xffffffffu, sum, 2);
            float inv = 1.f / sum;
#pragma unroll
            for (int ni = 0; ni < 8; ni++) {
                sacc[mi][ni][hf * 2 + 0] *= inv;
                sacc[mi][ni][hf * 2 + 1] *= inv;
            }
        }
    }

    unsigned pfr[2][4][4];
#pragma unroll
    for (int mi = 0; mi < 2; mi++)
#pragma unroll
        for (int q = 0; q < 4; q++) {
            pfr[mi][q][0] = packh(sacc[mi][2 * q][0],     sacc[mi][2 * q][1]);
            pfr[mi][q][1] = packh(sacc[mi][2 * q][2],     sacc[mi][2 * q][3]);
            pfr[mi][q][2] = packh(sacc[mi][2 * q + 1][0], sacc[mi][2 * q + 1][1]);
            pfr[mi][q][3] = packh(sacc[mi][2 * q + 1][2], sacc[mi][2 * q + 1][3]);
        }

    float oacc[2][4][4];
#pragma unroll
    for (int mi = 0; mi < 2; mi++)
#pragma unroll
        for (int nj = 0; nj < 4; nj++)
#pragma unroll
            for (int r = 0; r < 4; r++) oacc[mi][nj][r] = 0.f;

#pragma unroll
    for (int q = 0; q < 4; q++) {
        unsigned bv[4][2];
#pragma unroll
        for (int nj = 0; nj < 4; nj++) {
            unsigned addr = sptr(&vs[q * 16 + (lane & 15)][co + nj * 8]);
            asm volatile("ldmatrix.sync.aligned.m8n8.x2.trans.shared.b16 {%0,%1},[%2];"
                : "=r"(bv[nj][0]), "=r"(bv[nj][1]) : "r"(addr));
        }
#pragma unroll
        for (int mi = 0; mi < 2; mi++)
#pragma unroll
            for (int nj = 0; nj < 4; nj++)
                asm volatile("mma.sync.aligned.m16n8k16.row.col.f32.f16.f16.f32 "
                    "{%0,%1,%2,%3},{%4,%5,%6,%7},{%8,%9},{%0,%1,%2,%3};"
                    : "+f"(oacc[mi][nj][0]), "+f"(oacc[mi][nj][1]),
                      "+f"(oacc[mi][nj][2]), "+f"(oacc[mi][nj][3])
                    : "r"(pfr[mi][q][0]), "r"(pfr[mi][q][1]), "r"(pfr[mi][q][2]), "r"(pfr[mi][q][3]),
                      "r"(bv[nj][0]), "r"(bv[nj][1]));
    }

    int hgl = hb * 2 + hh;
#pragma unroll
    for (int mi = 0; mi < 2; mi++)
#pragma unroll
        for (int hf = 0; hf < 2; hf++) {
            int l = wr * 32 + mi * 16 + hf * 8 + lq;
            fp16* op = out + (size_t)(w * 64 + l) * HDIM + hgl * 32 + lc2;
#pragma unroll
            for (int nj = 0; nj < 4; nj++)
                *(fp162*)(op + nj * 8) =
                    __floats2half2_rn(oacc[mi][nj][hf * 2 + 0], oacc[mi][nj][hf * 2 + 1]);
        }
}

// ---------------- launch -----------------------------------------------------
extern "C" void kernel_launch(void* const* d_in, const int* in_sizes, int n_in,
                              void* d_out, int out_size)
{
    (void)in_sizes; (void)n_in; (void)out_size;
    const float* x     = (const float*)d_in[0];
    const float* n1w   = (const float*)d_in[1];
    const float* n1b   = (const float*)d_in[2];
    const float* qkvw  = (const float*)d_in[3];
    const float* qkvb  = (const float*)d_in[4];
    const float* projw = (const float*)d_in[5];
    const float* projb = (const float*)d_in[6];
    const float* relt  = (const float*)d_in[7];
    const float* g1    = (const float*)d_in[8];
    const float* n2w   = (const float*)d_in[9];
    const float* n2b   = (const float*)d_in[10];
    const float* fc1w  = (const float*)d_in[11];
    const float* fc1b  = (const float*)d_in[12];
    const float* fc2w  = (const float*)d_in[13];
    const float* fc2b  = (const float*)d_in[14];
    const float* g2    = (const float*)d_in[15];
    float* out = (float*)d_out;

    float *p_win, *p_o1;
    fp16 *p_xnb, *p_qkvb, *p_attb, *p_hb, *p_wq, *p_wp, *p_w1, *p_w2;
    cudaGetSymbolAddress((void**)&p_win,  g_win);
    cudaGetSymbolAddress((void**)&p_o1,   g_o1);
    cudaGetSymbolAddress((void**)&p_xnb,  g_xnb);
    cudaGetSymbolAddress((void**)&p_qkvb, g_qkvb);
    cudaGetSymbolAddress((void**)&p_attb, g_attb);
    cudaGetSymbolAddress((void**)&p_hb,   g_hb);
    cudaGetSymbolAddress((void**)&p_wq,   g_wq);
    cudaGetSymbolAddress((void**)&p_wp,   g_wp);
    cudaGetSymbolAddress((void**)&p_w1,   g_w1);
    cudaGetSymbolAddress((void**)&p_w2,   g_w2);

    cudaFuncSetAttribute(hgemm_kernel<0, fp16>,
        cudaFuncAttributeMaxDynamicSharedMemorySize, GSMEM);
    cudaFuncSetAttribute(hgemm_kernel<1, fp16>,
        cudaFuncAttributeMaxDynamicSharedMemorySize, GSMEM);
    cudaFuncSetAttribute(hgemm_kernel<2, float>,
        cudaFuncAttributeMaxDynamicSharedMemorySize, GSMEM);
    cudaFuncSetAttribute(partln_kernel,
        cudaFuncAttributeMaxDynamicSharedMemorySize, 512 * 33 * 4);

    f2h_all_kernel<<<dim3(1024, 4), 256>>>(qkvw, projw, fc1w, fc2w,
                                           p_wq, p_wp, p_w1, p_w2);

    partln_kernel<<<NTOK / 32, 256, 512 * 33 * 4>>>(x, p_win, p_xnb, n1w, n1b);

    hgemm_kernel<0, fp16><<<dim3(3 * HDIM / GBN, NTOK / GBM), 256, GSMEM>>>(
        p_xnb, p_wq, qkvb, p_qkvb, NTOK, 3 * HDIM, HDIM, nullptr, nullptr);
    attn_mma_kernel<<<dim3(NW, 8), 128>>>(p_qkvb, relt, p_attb);
    hgemm_kernel<2, float><<<dim3(HDIM / GBN, NTOK / GBM), 256, GSMEM>>>(
        p_attb, p_wp, projb, p_o1, NTOK, HDIM, HDIM, p_win, g1);
    ln_kernel<<<NTOK / 8, 256>>>(p_o1, p_xnb, n2w, n2b);
    hgemm_kernel<1, fp16><<<dim3(4 * HDIM / GBN, NTOK / GBM), 256, GSMEM>>>(
        p_xnb, p_w1, fc1b, p_hb, NTOK, 4 * HDIM, HDIM, nullptr, nullptr);
    hgemm_kernel<2, float><<<dim3(HDIM / GBN, NTOK / GBM), 256, GSMEM>>>(
        p_hb, p_w2, fc2b, p_win, NTOK, HDIM, 4 * HDIM, p_o1, g2);

    dim3 tp(32, 8);
    reverse_kernel<<<dim3(NTOK / 32, HDIM / 32), tp>>>(p_win, out);
}